// round 1
// baseline (speedup 1.0000x reference)
#include <cuda_runtime.h>
#include <math.h>

#define BB 2
#define SS 2048
#define DD 1024
#define HH 16
#define DHH 64
#define MM (BB*SS)   // 4096 rows

// ---------------- scratch (device globals; no allocation allowed) ----------
__device__ float buf_xn[MM*DD];
__device__ float buf_qkv[MM*3*DD];
__device__ float buf_attn[MM*DD];
__device__ float buf_u[MM*DD];
__device__ float buf_o[MM*DD];
__device__ float buf_on[MM*DD];
__device__ float buf_x12[MM*2*DD];
__device__ float buf_hidden[MM*DD];

// ---------------- RMSNorm: one block per row, 256 threads, float4 ----------
__global__ void rmsnorm_kernel(const float* __restrict__ x,
                               const float* __restrict__ g,
                               float* __restrict__ out) {
    const int row = blockIdx.x;
    const int t = threadIdx.x;                       // 256 threads * float4 = 1024
    float4 v = reinterpret_cast<const float4*>(x)[(size_t)row*(DD/4) + t];
    float ss = v.x*v.x + v.y*v.y + v.z*v.z + v.w*v.w;
    #pragma unroll
    for (int o = 16; o > 0; o >>= 1) ss += __shfl_xor_sync(0xffffffffu, ss, o);
    __shared__ float sred[8];
    if ((t & 31) == 0) sred[t >> 5] = ss;
    __syncthreads();
    float tot = 0.f;
    #pragma unroll
    for (int i = 0; i < 8; i++) tot += sred[i];
    const float sc = rsqrtf(tot * (1.0f/DD) + 1e-8f);
    float4 gv = reinterpret_cast<const float4*>(g)[t];
    float4 r;
    r.x = v.x*gv.x*sc; r.y = v.y*gv.y*sc; r.z = v.z*gv.z*sc; r.w = v.w*gv.w*sc;
    reinterpret_cast<float4*>(out)[(size_t)row*(DD/4) + t] = r;
}

// ---------------- generic SGEMM: C[M,N] = A[M,K] * B[N,K]^T ----------------
// MODE 0: plain   MODE 1: silu(C)   MODE 2: C + aux (residual)
template<int MODE>
__global__ void sgemm_nt(const float* __restrict__ A, const float* __restrict__ Bm,
                         const float* __restrict__ aux, float* __restrict__ C,
                         int M, int N, int K) {
    __shared__ float As[16][64];
    __shared__ float Bs[16][64];
    const int bm = blockIdx.y * 64, bn = blockIdx.x * 64;
    const int tid = threadIdx.x;
    const int tx = tid & 15, ty = tid >> 4;
    float acc[4][4] = {};
    for (int k0 = 0; k0 < K; k0 += 16) {
        #pragma unroll
        for (int i = 0; i < 4; i++) {
            int idx = tid + i*256;                   // 1024 elems per tile
            int r = idx >> 4, c = idx & 15;
            As[c][r] = A[(size_t)(bm + r)*K + (k0 + c)];
            Bs[c][r] = Bm[(size_t)(bn + r)*K + (k0 + c)];
        }
        __syncthreads();
        #pragma unroll
        for (int kk = 0; kk < 16; kk++) {
            float a[4], b[4];
            #pragma unroll
            for (int i = 0; i < 4; i++) a[i] = As[kk][ty*4 + i];
            #pragma unroll
            for (int j = 0; j < 4; j++) b[j] = Bs[kk][tx*4 + j];
            #pragma unroll
            for (int i = 0; i < 4; i++)
                #pragma unroll
                for (int j = 0; j < 4; j++)
                    acc[i][j] = fmaf(a[i], b[j], acc[i][j]);
        }
        __syncthreads();
    }
    #pragma unroll
    for (int i = 0; i < 4; i++) {
        const int m = bm + ty*4 + i;
        #pragma unroll
        for (int j = 0; j < 4; j++) {
            const int n = bn + tx*4 + j;
            float v = acc[i][j];
            if (MODE == 1) v = v / (1.f + __expf(-v));
            if (MODE == 2) v += aux[(size_t)m*N + n];
            C[(size_t)m*N + n] = v;
        }
    }
}

// ---------------- fused causal silu-attention (flash-style, no softmax) ----
// grid: (S/64, H, B). 64x64 Q tile, stream K/V tiles; never materialize SxS.
__global__ void attn_kernel(const float* __restrict__ pbias) {
    extern __shared__ float sm[];
    float* Qs = sm;               // [64][65]  Qs[d*65+q]   (pre-scaled)
    float* Ks = sm + 64*65;       // Ks[d*65+k]
    float* Vs = sm + 2*64*65;     // Vs[k*65+d]
    float* Ps = sm + 3*64*65;     // Ps[k*65+q]
    const int qb = blockIdx.x, h = blockIdx.y, b = blockIdx.z;
    const int tid = threadIdx.x, tx = tid & 15, ty = tid >> 4;
    const float scale = 0.125f;   // 1/sqrt(64)

    #pragma unroll
    for (int i = 0; i < 16; i++) {
        int idx = tid + i*256;
        int r = idx >> 6, d = idx & 63;
        size_t s = (size_t)b*SS + qb*64 + r;
        Qs[d*65 + r] = buf_qkv[((s*3 + 0)*HH + h)*DHH + d] * scale;
    }

    float acc[4][4] = {};
    for (int kt = 0; kt <= qb; kt++) {
        __syncthreads();          // protect Ks/Vs/Ps from prev iter (and Qs on first)
        #pragma unroll
        for (int i = 0; i < 16; i++) {
            int idx = tid + i*256;
            int r = idx >> 6, d = idx & 63;
            size_t s = (size_t)b*SS + kt*64 + r;
            Ks[d*65 + r] = buf_qkv[((s*3 + 1)*HH + h)*DHH + d];
            Vs[r*65 + d] = buf_qkv[((s*3 + 2)*HH + h)*DHH + d];
        }
        __syncthreads();

        // S = (Q*scale) @ K^T   (64x64x64)
        float sv[4][4] = {};
        #pragma unroll 8
        for (int d = 0; d < 64; d++) {
            float a[4], bv[4];
            #pragma unroll
            for (int i = 0; i < 4; i++) a[i] = Qs[d*65 + ty*4 + i];
            #pragma unroll
            for (int j = 0; j < 4; j++) bv[j] = Ks[d*65 + tx*4 + j];
            #pragma unroll
            for (int i = 0; i < 4; i++)
                #pragma unroll
                for (int j = 0; j < 4; j++)
                    sv[i][j] = fmaf(a[i], bv[j], sv[i][j]);
        }
        // bias + causal mask + silu -> Ps[k][q]
        #pragma unroll
        for (int i = 0; i < 4; i++) {
            const int qg = qb*64 + ty*4 + i;
            #pragma unroll
            for (int j = 0; j < 4; j++) {
                const int kg = kt*64 + tx*4 + j;
                float v = 0.f;
                if (kg <= qg) {
                    float s2 = sv[i][j] + pbias[((size_t)h*SS + qg)*SS + kg];
                    v = s2 / (1.f + __expf(-s2));
                }
                Ps[(tx*4 + j)*65 + (ty*4 + i)] = v;
            }
        }
        __syncthreads();

        // acc[q][dh] += P[q][k] * V[k][dh]
        #pragma unroll 8
        for (int kk = 0; kk < 64; kk++) {
            float a[4], bv[4];
            #pragma unroll
            for (int i = 0; i < 4; i++) a[i] = Ps[kk*65 + ty*4 + i];
            #pragma unroll
            for (int j = 0; j < 4; j++) bv[j] = Vs[kk*65 + tx*4 + j];
            #pragma unroll
            for (int i = 0; i < 4; i++)
                #pragma unroll
                for (int j = 0; j < 4; j++)
                    acc[i][j] = fmaf(a[i], bv[j], acc[i][j]);
        }
    }

    #pragma unroll
    for (int i = 0; i < 4; i++) {
        size_t q = (size_t)b*SS + qb*64 + ty*4 + i;
        #pragma unroll
        for (int j = 0; j < 4; j++)
            buf_attn[q*DD + h*DHH + tx*4 + j] = acc[i][j];
    }
}

// ---------------- elementwise ---------------------------------------------
__global__ void mul_kernel() {
    int i = blockIdx.x * blockDim.x + threadIdx.x;
    buf_attn[i] *= buf_u[i];       // ams = attn * u (in place)
}

__global__ void swiglu_kernel() {
    int i = blockIdx.x * blockDim.x + threadIdx.x;
    int m = i >> 10, d = i & 1023;
    float a  = buf_x12[(size_t)m*2048 + d];
    float b2 = buf_x12[(size_t)m*2048 + 1024 + d];
    buf_hidden[i] = a / (1.f + __expf(-a)) * b2;
}

// ---------------- launch ----------------------------------------------------
extern "C" void kernel_launch(void* const* d_in, const int* in_sizes, int n_in,
                              void* d_out, int out_size) {
    const float* x      = (const float*)d_in[0];
    const float* p_bias = (const float*)d_in[1];
    // d_in[2] = mask : exactly causal; handled analytically in attn_kernel
    const float* w_qkv  = (const float*)d_in[3];
    const float* w_u    = (const float*)d_in[4];
    const float* gams   = (const float*)d_in[5];
    const float* w0     = (const float*)d_in[6];
    const float* w1     = (const float*)d_in[7];
    const float* w3     = (const float*)d_in[8];
    const float* gmffn  = (const float*)d_in[9];
    float* out = (float*)d_out;

    float *xn, *qkv, *attn, *u, *o, *on, *x12, *hidden;
    cudaGetSymbolAddress((void**)&xn,     buf_xn);
    cudaGetSymbolAddress((void**)&qkv,    buf_qkv);
    cudaGetSymbolAddress((void**)&attn,   buf_attn);
    cudaGetSymbolAddress((void**)&u,      buf_u);
    cudaGetSymbolAddress((void**)&o,      buf_o);
    cudaGetSymbolAddress((void**)&on,     buf_on);
    cudaGetSymbolAddress((void**)&x12,    buf_x12);
    cudaGetSymbolAddress((void**)&hidden, buf_hidden);

    const int attn_smem = 4 * 64 * 65 * (int)sizeof(float);   // 66560 B
    cudaFuncSetAttribute(attn_kernel, cudaFuncAttributeMaxDynamicSharedMemorySize, attn_smem);

    // 1) xn = rmsnorm(x, g_ams)
    rmsnorm_kernel<<<MM, 256>>>(x, gams, xn);
    // 2) qkv = xn @ w_qkv^T
    sgemm_nt<0><<<dim3(3*DD/64, MM/64), 256>>>(xn, w_qkv, nullptr, qkv, MM, 3*DD, DD);
    // 3) attn = silu-attention(q,k,v, p_bias, causal)
    attn_kernel<<<dim3(SS/64, HH, BB), 256, attn_smem>>>(p_bias);
    // 4) u = silu(xn @ w_u^T)
    sgemm_nt<1><<<dim3(DD/64, MM/64), 256>>>(xn, w_u, nullptr, u, MM, DD, DD);
    // 5) ams = attn * u (in place in buf_attn)
    mul_kernel<<<MM*DD/256, 256>>>();
    // 6) o = ams @ w0^T + x
    sgemm_nt<2><<<dim3(DD/64, MM/64), 256>>>(attn, w0, x, o, MM, DD, DD);
    // 7) on = rmsnorm(o, g_mffn)
    rmsnorm_kernel<<<MM, 256>>>(o, gmffn, on);
    // 8) x12 = on @ w1^T
    sgemm_nt<0><<<dim3(2*DD/64, MM/64), 256>>>(on, w1, nullptr, x12, MM, 2*DD, DD);
    // 9) hidden = silu(x1) * x2
    swiglu_kernel<<<MM*DD/256, 256>>>();
    // 10) out = hidden @ w3^T + o
    sgemm_nt<2><<<dim3(DD/64, MM/64), 256>>>(hidden, w3, o, out, MM, DD, DD);
}

// round 3
// speedup vs baseline: 2.8640x; 2.8640x over previous
#include <cuda_runtime.h>
#include <cuda_bf16.h>
#include <cstdint>
#include <math.h>

#define BB 2
#define SS 2048
#define DD 1024
#define HH 16
#define DHH 64
#define MM (BB*SS)   // 4096 rows

// ---------------- scratch (device globals; no allocation allowed) ----------
__device__ float buf_qkv [MM*3*DD];
__device__ float buf_attn[MM*DD];
__device__ float buf_u   [MM*DD];
__device__ float buf_o   [MM*DD];
__device__ float buf_x12 [MM*2*DD];

__device__ __nv_bfloat16 buf_xn_hi [MM*DD],   buf_xn_lo [MM*DD];
__device__ __nv_bfloat16 buf_on_hi [MM*DD],   buf_on_lo [MM*DD];
__device__ __nv_bfloat16 buf_ams_hi[MM*DD],   buf_ams_lo[MM*DD];
__device__ __nv_bfloat16 buf_hid_hi[MM*DD],   buf_hid_lo[MM*DD];

__device__ __nv_bfloat16 wqkv_hi[3*DD*DD], wqkv_lo[3*DD*DD];
__device__ __nv_bfloat16 wu_hi  [DD*DD],   wu_lo  [DD*DD];
__device__ __nv_bfloat16 w0_hi  [DD*DD],   w0_lo  [DD*DD];
__device__ __nv_bfloat16 w1_hi  [2*DD*DD], w1_lo  [2*DD*DD];
__device__ __nv_bfloat16 w3_hi  [DD*DD],   w3_lo  [DD*DD];

// ---------------- PTX helpers (sm_80+ portable only) ------------------------
__device__ __forceinline__ uint32_t smem_u32(const void* p) {
    uint32_t a;
    asm("{ .reg .u64 t; cvta.to.shared.u64 t, %1; cvt.u32.u64 %0, t; }" : "=r"(a) : "l"(p));
    return a;
}
__device__ __forceinline__ void cp16(uint32_t saddr, const void* g) {
    asm volatile("cp.async.cg.shared.global [%0], [%1], 16;" :: "r"(saddr), "l"(g));
}
#define CP_COMMIT() asm volatile("cp.async.commit_group;" ::: "memory")
#define CP_WAIT2()  asm volatile("cp.async.wait_group 2;"  ::: "memory")

__device__ __forceinline__ void ldsm4(uint32_t (&r)[4], uint32_t addr) {
    asm volatile("ldmatrix.sync.aligned.m8n8.x4.shared.b16 {%0,%1,%2,%3}, [%4];"
                 : "=r"(r[0]), "=r"(r[1]), "=r"(r[2]), "=r"(r[3]) : "r"(addr));
}
__device__ __forceinline__ void mma16816(float (&d)[4], const uint32_t (&a)[4],
                                         uint32_t b0, uint32_t b1) {
    asm volatile(
        "mma.sync.aligned.m16n8k16.row.col.f32.bf16.bf16.f32 "
        "{%0,%1,%2,%3}, {%4,%5,%6,%7}, {%8,%9}, {%0,%1,%2,%3};"
        : "+f"(d[0]), "+f"(d[1]), "+f"(d[2]), "+f"(d[3])
        : "r"(a[0]), "r"(a[1]), "r"(a[2]), "r"(a[3]), "r"(b0), "r"(b1));
}

// ---------------- conversion: fp32 -> (bf16 hi, bf16 lo) --------------------
__device__ __forceinline__ void split1(float x, __nv_bfloat16& h, __nv_bfloat16& l) {
    h = __float2bfloat16(x);
    l = __float2bfloat16(x - __bfloat162float(h));
}
__global__ void cvt_hilo(const float* __restrict__ in,
                         __nv_bfloat16* __restrict__ hi,
                         __nv_bfloat16* __restrict__ lo, int n4) {
    int i = blockIdx.x * blockDim.x + threadIdx.x;
    if (i >= n4) return;
    float4 v = reinterpret_cast<const float4*>(in)[i];
    __nv_bfloat16 h[4], l[4];
    split1(v.x, h[0], l[0]); split1(v.y, h[1], l[1]);
    split1(v.z, h[2], l[2]); split1(v.w, h[3], l[3]);
    reinterpret_cast<uint2*>(hi)[i] = *reinterpret_cast<uint2*>(h);
    reinterpret_cast<uint2*>(lo)[i] = *reinterpret_cast<uint2*>(l);
}

// ---------------- RMSNorm -> hi/lo bf16 --------------------------------------
__global__ void rmsnorm_hilo(const float* __restrict__ x, const float* __restrict__ g,
                             __nv_bfloat16* __restrict__ hi, __nv_bfloat16* __restrict__ lo) {
    const int row = blockIdx.x;
    const int t = threadIdx.x;                        // 256 threads * float4
    float4 v = reinterpret_cast<const float4*>(x)[(size_t)row*(DD/4) + t];
    float ss = v.x*v.x + v.y*v.y + v.z*v.z + v.w*v.w;
    #pragma unroll
    for (int o = 16; o > 0; o >>= 1) ss += __shfl_xor_sync(0xffffffffu, ss, o);
    __shared__ float sred[8];
    if ((t & 31) == 0) sred[t >> 5] = ss;
    __syncthreads();
    float tot = 0.f;
    #pragma unroll
    for (int i = 0; i < 8; i++) tot += sred[i];
    const float sc = rsqrtf(tot * (1.0f/DD) + 1e-8f);
    float4 gv = reinterpret_cast<const float4*>(g)[t];
    float r0 = v.x*gv.x*sc, r1 = v.y*gv.y*sc, r2 = v.z*gv.z*sc, r3 = v.w*gv.w*sc;
    __nv_bfloat16 h[4], l[4];
    split1(r0, h[0], l[0]); split1(r1, h[1], l[1]);
    split1(r2, h[2], l[2]); split1(r3, h[3], l[3]);
    reinterpret_cast<uint2*>(hi)[(size_t)row*(DD/4) + t] = *reinterpret_cast<uint2*>(h);
    reinterpret_cast<uint2*>(lo)[(size_t)row*(DD/4) + t] = *reinterpret_cast<uint2*>(l);
}

// ---------------- mma.sync GEMM: C[M,N] = A[M,K] * B[N,K]^T  (bf16x3) -------
// block tile 128x128, Kc=64, 8 warps (2m x 4n), warp tile 64x32.
// MODE 0: plain   MODE 1: silu(C)   MODE 2: C + aux
#define KC 64
#define NSTAGE 3
#define TILE_B 16384                 // one 128x64 bf16 tile
#define STAGE_BYTES (4*TILE_B)       // Ahi, Alo, Bhi, Blo
#define GEMM_SMEM (NSTAGE*STAGE_BYTES)   // 196608

// swizzled smem byte offset for (row, 16B-granule g)
__device__ __forceinline__ uint32_t swz(int row, int g) {
    return (uint32_t)(row * 128 + ((g ^ (row & 7)) << 4));
}

template<int MODE>
__global__ void __launch_bounds__(256, 1)
gemm_bf16x3(const __nv_bfloat16* __restrict__ Ahi, const __nv_bfloat16* __restrict__ Alo,
            const __nv_bfloat16* __restrict__ Bhi, const __nv_bfloat16* __restrict__ Blo,
            const float* __restrict__ aux, float* __restrict__ C,
            int M, int N, int K) {
    extern __shared__ char smraw[];
    const uint32_t sb = smem_u32(smraw);
    const int tid = threadIdx.x;
    const int lane = tid & 31, wid = tid >> 5;
    const int warp_m = wid >> 2, warp_n = wid & 3;    // 2 x 4
    const int bm = blockIdx.y * 128, bn = blockIdx.x * 128;
    const int nchunks = K / KC;

    // global load helper: 4 uint4 per tile per thread
    auto load_chunk = [&](int c) {
        const int st = c % NSTAGE;
        const uint32_t stb = sb + st * STAGE_BYTES;
        const int k0 = c * KC;
        #pragma unroll
        for (int i = 0; i < 4; i++) {
            int idx = tid + i * 256;
            int r = idx >> 3, g = idx & 7;
            uint32_t so = swz(r, g);
            size_t ga = (size_t)(bm + r) * K + k0 + g * 8;
            size_t gb = (size_t)(bn + r) * K + k0 + g * 8;
            cp16(stb + so,              Ahi + ga);
            cp16(stb + TILE_B + so,     Alo + ga);
            cp16(stb + 2*TILE_B + so,   Bhi + gb);
            cp16(stb + 3*TILE_B + so,   Blo + gb);
        }
    };

    float acc[4][4][4] = {};

    load_chunk(0); CP_COMMIT();
    load_chunk(1); CP_COMMIT();

    for (int c = 0; c < nchunks; ++c) {
        if (c + 2 < nchunks) load_chunk(c + 2);
        CP_COMMIT();
        CP_WAIT2();
        __syncthreads();

        const uint32_t stb = sb + (c % NSTAGE) * STAGE_BYTES;
        const uint32_t aH = stb, aL = stb + TILE_B, bH = stb + 2*TILE_B, bL = stb + 3*TILE_B;
        const int lrow = lane & 15, lg = lane >> 4;

        #pragma unroll
        for (int ks = 0; ks < 4; ++ks) {
            const int kkg = ks * 2;
            uint32_t Ah[4][4], Al[4][4], Bh[2][4], Bl[2][4];
            #pragma unroll
            for (int mt = 0; mt < 4; ++mt) {
                int row = warp_m * 64 + mt * 16 + lrow;
                uint32_t so = swz(row, kkg + lg);
                ldsm4(Ah[mt], aH + so);
                ldsm4(Al[mt], aL + so);
            }
            #pragma unroll
            for (int nt2 = 0; nt2 < 2; ++nt2) {
                int row = warp_n * 32 + nt2 * 16 + lrow;
                uint32_t so = swz(row, kkg + lg);
                ldsm4(Bh[nt2], bH + so);
                ldsm4(Bl[nt2], bL + so);
            }
            #pragma unroll
            for (int mt = 0; mt < 4; ++mt) {
                #pragma unroll
                for (int nt = 0; nt < 4; ++nt) {
                    const int j = nt >> 1, h = nt & 1;
                    mma16816(acc[mt][nt], Ah[mt], Bh[j][h], Bh[j][h+2]);
                    mma16816(acc[mt][nt], Ah[mt], Bl[j][h], Bl[j][h+2]);
                    mma16816(acc[mt][nt], Al[mt], Bh[j][h], Bh[j][h+2]);
                }
            }
        }
        __syncthreads();
    }

    // epilogue: each thread owns rows (lane>>2, +8), cols (lane&3)*2, +1 per tile
    #pragma unroll
    for (int mt = 0; mt < 4; ++mt) {
        #pragma unroll
        for (int nt = 0; nt < 4; ++nt) {
            const int m0 = bm + warp_m * 64 + mt * 16 + (lane >> 2);
            const int n0 = bn + warp_n * 32 + nt * 8 + (lane & 3) * 2;
            #pragma unroll
            for (int half = 0; half < 2; ++half) {
                const int m = m0 + half * 8;
                float2 v = make_float2(acc[mt][nt][half*2], acc[mt][nt][half*2+1]);
                if (MODE == 1) {
                    v.x = v.x / (1.f + __expf(-v.x));
                    v.y = v.y / (1.f + __expf(-v.y));
                }
                if (MODE == 2) {
                    float2 a = *reinterpret_cast<const float2*>(aux + (size_t)m * N + n0);
                    v.x += a.x; v.y += a.y;
                }
                *reinterpret_cast<float2*>(C + (size_t)m * N + n0) = v;
            }
        }
    }
}

// ---------------- fused causal silu-attention (scalar, unchanged) -----------
__global__ void attn_kernel(const float* __restrict__ pbias) {
    extern __shared__ float sm[];
    float* Qs = sm;               // [64][65]  Qs[d*65+q]   (pre-scaled)
    float* Ks = sm + 64*65;
    float* Vs = sm + 2*64*65;
    float* Ps = sm + 3*64*65;
    const int qb = blockIdx.x, h = blockIdx.y, b = blockIdx.z;
    const int tid = threadIdx.x, tx = tid & 15, ty = tid >> 4;
    const float scale = 0.125f;

    #pragma unroll
    for (int i = 0; i < 16; i++) {
        int idx = tid + i*256;
        int r = idx >> 6, d = idx & 63;
        size_t s = (size_t)b*SS + qb*64 + r;
        Qs[d*65 + r] = buf_qkv[((s*3 + 0)*HH + h)*DHH + d] * scale;
    }

    float acc[4][4] = {};
    for (int kt = 0; kt <= qb; kt++) {
        __syncthreads();
        #pragma unroll
        for (int i = 0; i < 16; i++) {
            int idx = tid + i*256;
            int r = idx >> 6, d = idx & 63;
            size_t s = (size_t)b*SS + kt*64 + r;
            Ks[d*65 + r] = buf_qkv[((s*3 + 1)*HH + h)*DHH + d];
            Vs[r*65 + d] = buf_qkv[((s*3 + 2)*HH + h)*DHH + d];
        }
        __syncthreads();

        float sv[4][4] = {};
        #pragma unroll 8
        for (int d = 0; d < 64; d++) {
            float a[4], bv[4];
            #pragma unroll
            for (int i = 0; i < 4; i++) a[i] = Qs[d*65 + ty*4 + i];
            #pragma unroll
            for (int j = 0; j < 4; j++) bv[j] = Ks[d*65 + tx*4 + j];
            #pragma unroll
            for (int i = 0; i < 4; i++)
                #pragma unroll
                for (int j = 0; j < 4; j++)
                    sv[i][j] = fmaf(a[i], bv[j], sv[i][j]);
        }
        #pragma unroll
        for (int i = 0; i < 4; i++) {
            const int qg = qb*64 + ty*4 + i;
            #pragma unroll
            for (int j = 0; j < 4; j++) {
                const int kg = kt*64 + tx*4 + j;
                float v = 0.f;
                if (kg <= qg) {
                    float s2 = sv[i][j] + pbias[((size_t)h*SS + qg)*SS + kg];
                    v = s2 / (1.f + __expf(-s2));
                }
                Ps[(tx*4 + j)*65 + (ty*4 + i)] = v;
            }
        }
        __syncthreads();

        #pragma unroll 8
        for (int kk = 0; kk < 64; kk++) {
            float a[4], bv[4];
            #pragma unroll
            for (int i = 0; i < 4; i++) a[i] = Ps[kk*65 + ty*4 + i];
            #pragma unroll
            for (int j = 0; j < 4; j++) bv[j] = Vs[kk*65 + tx*4 + j];
            #pragma unroll
            for (int i = 0; i < 4; i++)
                #pragma unroll
                for (int j = 0; j < 4; j++)
                    acc[i][j] = fmaf(a[i], bv[j], acc[i][j]);
        }
    }

    #pragma unroll
    for (int i = 0; i < 4; i++) {
        size_t q = (size_t)b*SS + qb*64 + ty*4 + i;
        #pragma unroll
        for (int j = 0; j < 4; j++)
            buf_attn[q*DD + h*DHH + tx*4 + j] = acc[i][j];
    }
}

// ---------------- elementwise (write hi/lo) ----------------------------------
__global__ void mul_hilo() {
    int i = blockIdx.x * blockDim.x + threadIdx.x;       // per float4
    float4 a = reinterpret_cast<const float4*>(buf_attn)[i];
    float4 u = reinterpret_cast<const float4*>(buf_u)[i];
    __nv_bfloat16 h[4], l[4];
    split1(a.x*u.x, h[0], l[0]); split1(a.y*u.y, h[1], l[1]);
    split1(a.z*u.z, h[2], l[2]); split1(a.w*u.w, h[3], l[3]);
    reinterpret_cast<uint2*>(buf_ams_hi)[i] = *reinterpret_cast<uint2*>(h);
    reinterpret_cast<uint2*>(buf_ams_lo)[i] = *reinterpret_cast<uint2*>(l);
}

__global__ void swiglu_hilo() {
    int i = blockIdx.x * blockDim.x + threadIdx.x;       // per float4 of hidden
    int m = i >> 8, d4 = i & 255;                        // DD/4 = 256
    float4 a  = reinterpret_cast<const float4*>(buf_x12)[(size_t)m*512 + d4];
    float4 b2 = reinterpret_cast<const float4*>(buf_x12)[(size_t)m*512 + 256 + d4];
    float r0 = a.x / (1.f + __expf(-a.x)) * b2.x;
    float r1 = a.y / (1.f + __expf(-a.y)) * b2.y;
    float r2 = a.z / (1.f + __expf(-a.z)) * b2.z;
    float r3 = a.w / (1.f + __expf(-a.w)) * b2.w;
    __nv_bfloat16 h[4], l[4];
    split1(r0, h[0], l[0]); split1(r1, h[1], l[1]);
    split1(r2, h[2], l[2]); split1(r3, h[3], l[3]);
    reinterpret_cast<uint2*>(buf_hid_hi)[i] = *reinterpret_cast<uint2*>(h);
    reinterpret_cast<uint2*>(buf_hid_lo)[i] = *reinterpret_cast<uint2*>(l);
}

// ---------------- launch ------------------------------------------------------
extern "C" void kernel_launch(void* const* d_in, const int* in_sizes, int n_in,
                              void* d_out, int out_size) {
    const float* x      = (const float*)d_in[0];
    const float* p_bias = (const float*)d_in[1];
    // d_in[2] = mask : exactly causal; handled analytically in attn_kernel
    const float* w_qkv  = (const float*)d_in[3];
    const float* w_u    = (const float*)d_in[4];
    const float* gams   = (const float*)d_in[5];
    const float* w0     = (const float*)d_in[6];
    const float* w1     = (const float*)d_in[7];
    const float* w3     = (const float*)d_in[8];
    const float* gmffn  = (const float*)d_in[9];
    float* out = (float*)d_out;

    float *qkv, *attn, *u, *o, *x12;
    __nv_bfloat16 *xnh, *xnl, *onh, *onl, *amsh, *amsl, *hidh, *hidl;
    __nv_bfloat16 *wqkvh, *wqkvl, *wuh, *wul, *w0h, *w0l, *w1h, *w1l, *w3h, *w3l;
    cudaGetSymbolAddress((void**)&qkv,  buf_qkv);
    cudaGetSymbolAddress((void**)&attn, buf_attn);
    cudaGetSymbolAddress((void**)&u,    buf_u);
    cudaGetSymbolAddress((void**)&o,    buf_o);
    cudaGetSymbolAddress((void**)&x12,  buf_x12);
    cudaGetSymbolAddress((void**)&xnh,  buf_xn_hi);  cudaGetSymbolAddress((void**)&xnl,  buf_xn_lo);
    cudaGetSymbolAddress((void**)&onh,  buf_on_hi);  cudaGetSymbolAddress((void**)&onl,  buf_on_lo);
    cudaGetSymbolAddress((void**)&amsh, buf_ams_hi); cudaGetSymbolAddress((void**)&amsl, buf_ams_lo);
    cudaGetSymbolAddress((void**)&hidh, buf_hid_hi); cudaGetSymbolAddress((void**)&hidl, buf_hid_lo);
    cudaGetSymbolAddress((void**)&wqkvh, wqkv_hi);   cudaGetSymbolAddress((void**)&wqkvl, wqkv_lo);
    cudaGetSymbolAddress((void**)&wuh,   wu_hi);     cudaGetSymbolAddress((void**)&wul,   wu_lo);
    cudaGetSymbolAddress((void**)&w0h,   w0_hi);     cudaGetSymbolAddress((void**)&w0l,   w0_lo);
    cudaGetSymbolAddress((void**)&w1h,   w1_hi);     cudaGetSymbolAddress((void**)&w1l,   w1_lo);
    cudaGetSymbolAddress((void**)&w3h,   w3_hi);     cudaGetSymbolAddress((void**)&w3l,   w3_lo);

    cudaFuncSetAttribute(gemm_bf16x3<0>, cudaFuncAttributeMaxDynamicSharedMemorySize, GEMM_SMEM);
    cudaFuncSetAttribute(gemm_bf16x3<1>, cudaFuncAttributeMaxDynamicSharedMemorySize, GEMM_SMEM);
    cudaFuncSetAttribute(gemm_bf16x3<2>, cudaFuncAttributeMaxDynamicSharedMemorySize, GEMM_SMEM);
    const int attn_smem = 4 * 64 * 65 * (int)sizeof(float);
    cudaFuncSetAttribute(attn_kernel, cudaFuncAttributeMaxDynamicSharedMemorySize, attn_smem);

    // 0) weight conversions (fp32 -> bf16 hi/lo)
    cvt_hilo<<<(3*DD*DD/4 + 255)/256, 256>>>(w_qkv, wqkvh, wqkvl, 3*DD*DD/4);
    cvt_hilo<<<(DD*DD/4   + 255)/256, 256>>>(w_u,   wuh,   wul,   DD*DD/4);
    cvt_hilo<<<(DD*DD/4   + 255)/256, 256>>>(w0,    w0h,   w0l,   DD*DD/4);
    cvt_hilo<<<(2*DD*DD/4 + 255)/256, 256>>>(w1,    w1h,   w1l,   2*DD*DD/4);
    cvt_hilo<<<(DD*DD/4   + 255)/256, 256>>>(w3,    w3h,   w3l,   DD*DD/4);

    // 1) xn = rmsnorm(x, g_ams) -> hi/lo
    rmsnorm_hilo<<<MM, 256>>>(x, gams, xnh, xnl);
    // 2) qkv = xn @ w_qkv^T
    gemm_bf16x3<0><<<dim3(3*DD/128, MM/128), 256, GEMM_SMEM>>>(xnh, xnl, wqkvh, wqkvl, nullptr, qkv, MM, 3*DD, DD);
    // 3) attn = silu-attention
    attn_kernel<<<dim3(SS/64, HH, BB), 256, attn_smem>>>(p_bias);
    // 4) u = silu(xn @ w_u^T)
    gemm_bf16x3<1><<<dim3(DD/128, MM/128), 256, GEMM_SMEM>>>(xnh, xnl, wuh, wul, nullptr, u, MM, DD, DD);
    // 5) ams = attn * u -> hi/lo
    mul_hilo<<<MM*DD/4/256, 256>>>();
    // 6) o = ams @ w0^T + x
    gemm_bf16x3<2><<<dim3(DD/128, MM/128), 256, GEMM_SMEM>>>(amsh, amsl, w0h, w0l, x, o, MM, DD, DD);
    // 7) on = rmsnorm(o, g_mffn) -> hi/lo
    rmsnorm_hilo<<<MM, 256>>>(o, gmffn, onh, onl);
    // 8) x12 = on @ w1^T
    gemm_bf16x3<0><<<dim3(2*DD/128, MM/128), 256, GEMM_SMEM>>>(onh, onl, w1h, w1l, nullptr, x12, MM, 2*DD, DD);
    // 9) hidden = silu(x1) * x2 -> hi/lo
    swiglu_hilo<<<MM*DD/4/256, 256>>>();
    // 10) out = hidden @ w3^T + o
    gemm_bf16x3<2><<<dim3(DD/128, MM/128), 256, GEMM_SMEM>>>(hidh, hidl, w3h, w3l, o, out, MM, DD, DD);
}

// round 4
// speedup vs baseline: 3.2460x; 1.1334x over previous
#include <cuda_runtime.h>
#include <cuda_bf16.h>
#include <cstdint>
#include <math.h>

#define BB 2
#define SS 2048
#define DD 1024
#define HH 16
#define DHH 64
#define MM (BB*SS)   // 4096 rows

// ---------------- scratch (device globals; no allocation allowed) ----------
__device__ float buf_qkv [MM*3*DD];
__device__ float buf_attn[MM*DD];
__device__ float buf_u   [MM*DD];
__device__ float buf_o   [MM*DD];
__device__ float buf_x12 [MM*2*DD];

__device__ __nv_bfloat16 buf_xn_hi [MM*DD],   buf_xn_lo [MM*DD];
__device__ __nv_bfloat16 buf_on_hi [MM*DD],   buf_on_lo [MM*DD];
__device__ __nv_bfloat16 buf_ams_hi[MM*DD],   buf_ams_lo[MM*DD];
__device__ __nv_bfloat16 buf_hid_hi[MM*DD],   buf_hid_lo[MM*DD];

// attention operand planes, [B,H,S,64]
#define QKV_PLANE (BB*HH*SS*DHH)
__device__ __nv_bfloat16 buf_q_hi[QKV_PLANE], buf_q_lo[QKV_PLANE];
__device__ __nv_bfloat16 buf_k_hi[QKV_PLANE], buf_k_lo[QKV_PLANE];
__device__ __nv_bfloat16 buf_v_hi[QKV_PLANE], buf_v_lo[QKV_PLANE];

__device__ __nv_bfloat16 wqkv_hi[3*DD*DD], wqkv_lo[3*DD*DD];
__device__ __nv_bfloat16 wu_hi  [DD*DD],   wu_lo  [DD*DD];
__device__ __nv_bfloat16 w0_hi  [DD*DD],   w0_lo  [DD*DD];
__device__ __nv_bfloat16 w1_hi  [2*DD*DD], w1_lo  [2*DD*DD];
__device__ __nv_bfloat16 w3_hi  [DD*DD],   w3_lo  [DD*DD];

// ---------------- PTX helpers (sm_80+ portable only) ------------------------
__device__ __forceinline__ uint32_t smem_u32(const void* p) {
    uint32_t a;
    asm("{ .reg .u64 t; cvta.to.shared.u64 t, %1; cvt.u32.u64 %0, t; }" : "=r"(a) : "l"(p));
    return a;
}
__device__ __forceinline__ void cp16(uint32_t saddr, const void* g) {
    asm volatile("cp.async.cg.shared.global [%0], [%1], 16;" :: "r"(saddr), "l"(g));
}
#define CP_COMMIT() asm volatile("cp.async.commit_group;" ::: "memory")

__device__ __forceinline__ void ldsm4(uint32_t (&r)[4], uint32_t addr) {
    asm volatile("ldmatrix.sync.aligned.m8n8.x4.shared.b16 {%0,%1,%2,%3}, [%4];"
                 : "=r"(r[0]), "=r"(r[1]), "=r"(r[2]), "=r"(r[3]) : "r"(addr));
}
__device__ __forceinline__ void ldsm4t(uint32_t (&r)[4], uint32_t addr) {
    asm volatile("ldmatrix.sync.aligned.m8n8.x4.trans.shared.b16 {%0,%1,%2,%3}, [%4];"
                 : "=r"(r[0]), "=r"(r[1]), "=r"(r[2]), "=r"(r[3]) : "r"(addr));
}
__device__ __forceinline__ void mma16816(float (&d)[4], const uint32_t (&a)[4],
                                         uint32_t b0, uint32_t b1) {
    asm volatile(
        "mma.sync.aligned.m16n8k16.row.col.f32.bf16.bf16.f32 "
        "{%0,%1,%2,%3}, {%4,%5,%6,%7}, {%8,%9}, {%0,%1,%2,%3};"
        : "+f"(d[0]), "+f"(d[1]), "+f"(d[2]), "+f"(d[3])
        : "r"(a[0]), "r"(a[1]), "r"(a[2]), "r"(a[3]), "r"(b0), "r"(b1));
}

// swizzled smem byte offset for (row, 16B-granule g), 128B rows
__device__ __forceinline__ uint32_t swz(int row, int g) {
    return (uint32_t)(row * 128 + ((g ^ (row & 7)) << 4));
}

// ---------------- conversion: fp32 -> (bf16 hi, bf16 lo) --------------------
__device__ __forceinline__ void split1(float x, __nv_bfloat16& h, __nv_bfloat16& l) {
    h = __float2bfloat16(x);
    l = __float2bfloat16(x - __bfloat162float(h));
}
__global__ void cvt_hilo(const float* __restrict__ in,
                         __nv_bfloat16* __restrict__ hi,
                         __nv_bfloat16* __restrict__ lo, int n4) {
    int i = blockIdx.x * blockDim.x + threadIdx.x;
    if (i >= n4) return;
    float4 v = reinterpret_cast<const float4*>(in)[i];
    __nv_bfloat16 h[4], l[4];
    split1(v.x, h[0], l[0]); split1(v.y, h[1], l[1]);
    split1(v.z, h[2], l[2]); split1(v.w, h[3], l[3]);
    reinterpret_cast<uint2*>(hi)[i] = *reinterpret_cast<uint2*>(h);
    reinterpret_cast<uint2*>(lo)[i] = *reinterpret_cast<uint2*>(l);
}

// qkv fp32 [b,s,3,h,d] -> per-tensor hi/lo planes [b,h,s,d] (q scaled by 1/8)
__global__ void cvt_qkv() {
    int i = blockIdx.x * blockDim.x + threadIdx.x;   // over MM*3*DD/4
    int dq = i & 15;
    int h  = (i >> 4) & 15;
    int t  = (i >> 8) % 3;
    int s  = i / 768;
    float4 v = reinterpret_cast<const float4*>(buf_qkv)[i];
    if (t == 0) { v.x *= 0.125f; v.y *= 0.125f; v.z *= 0.125f; v.w *= 0.125f; }
    int b = s >> 11, srow = s & 2047;
    size_t o4 = ((((size_t)b*HH + h)*SS + srow)*64 + dq*4) >> 2;   // uint2 index
    __nv_bfloat16 hh[4], ll[4];
    split1(v.x, hh[0], ll[0]); split1(v.y, hh[1], ll[1]);
    split1(v.z, hh[2], ll[2]); split1(v.w, hh[3], ll[3]);
    __nv_bfloat16 *dh, *dl;
    if      (t == 0) { dh = buf_q_hi; dl = buf_q_lo; }
    else if (t == 1) { dh = buf_k_hi; dl = buf_k_lo; }
    else             { dh = buf_v_hi; dl = buf_v_lo; }
    reinterpret_cast<uint2*>(dh)[o4] = *reinterpret_cast<uint2*>(hh);
    reinterpret_cast<uint2*>(dl)[o4] = *reinterpret_cast<uint2*>(ll);
}

// ---------------- RMSNorm -> hi/lo bf16 --------------------------------------
__global__ void rmsnorm_hilo(const float* __restrict__ x, const float* __restrict__ g,
                             __nv_bfloat16* __restrict__ hi, __nv_bfloat16* __restrict__ lo) {
    const int row = blockIdx.x;
    const int t = threadIdx.x;                        // 256 threads * float4
    float4 v = reinterpret_cast<const float4*>(x)[(size_t)row*(DD/4) + t];
    float ss = v.x*v.x + v.y*v.y + v.z*v.z + v.w*v.w;
    #pragma unroll
    for (int o = 16; o > 0; o >>= 1) ss += __shfl_xor_sync(0xffffffffu, ss, o);
    __shared__ float sred[8];
    if ((t & 31) == 0) sred[t >> 5] = ss;
    __syncthreads();
    float tot = 0.f;
    #pragma unroll
    for (int i = 0; i < 8; i++) tot += sred[i];
    const float sc = rsqrtf(tot * (1.0f/DD) + 1e-8f);
    float4 gv = reinterpret_cast<const float4*>(g)[t];
    float r0 = v.x*gv.x*sc, r1 = v.y*gv.y*sc, r2 = v.z*gv.z*sc, r3 = v.w*gv.w*sc;
    __nv_bfloat16 h[4], l[4];
    split1(r0, h[0], l[0]); split1(r1, h[1], l[1]);
    split1(r2, h[2], l[2]); split1(r3, h[3], l[3]);
    reinterpret_cast<uint2*>(hi)[(size_t)row*(DD/4) + t] = *reinterpret_cast<uint2*>(h);
    reinterpret_cast<uint2*>(lo)[(size_t)row*(DD/4) + t] = *reinterpret_cast<uint2*>(l);
}

// ---------------- mma.sync GEMM: C[M,N] = A[M,K] * B[N,K]^T  (bf16x3) -------
#define KC 64
#define NSTAGE 3
#define TILE_B 16384                 // one 128x64 bf16 tile
#define STAGE_BYTES (4*TILE_B)       // Ahi, Alo, Bhi, Blo
#define GEMM_SMEM (NSTAGE*STAGE_BYTES)   // 196608

template<int MODE>
__global__ void __launch_bounds__(256, 1)
gemm_bf16x3(const __nv_bfloat16* __restrict__ Ahi, const __nv_bfloat16* __restrict__ Alo,
            const __nv_bfloat16* __restrict__ Bhi, const __nv_bfloat16* __restrict__ Blo,
            const float* __restrict__ aux, float* __restrict__ C,
            int M, int N, int K) {
    extern __shared__ char smraw[];
    const uint32_t sb = smem_u32(smraw);
    const int tid = threadIdx.x;
    const int lane = tid & 31, wid = tid >> 5;
    const int warp_m = wid >> 2, warp_n = wid & 3;    // 2 x 4
    const int bm = blockIdx.y * 128, bn = blockIdx.x * 128;
    const int nchunks = K / KC;

    auto load_chunk = [&](int c) {
        const int st = c % NSTAGE;
        const uint32_t stb = sb + st * STAGE_BYTES;
        const int k0 = c * KC;
        #pragma unroll
        for (int i = 0; i < 4; i++) {
            int idx = tid + i * 256;
            int r = idx >> 3, g = idx & 7;
            uint32_t so = swz(r, g);
            size_t ga = (size_t)(bm + r) * K + k0 + g * 8;
            size_t gb = (size_t)(bn + r) * K + k0 + g * 8;
            cp16(stb + so,              Ahi + ga);
            cp16(stb + TILE_B + so,     Alo + ga);
            cp16(stb + 2*TILE_B + so,   Bhi + gb);
            cp16(stb + 3*TILE_B + so,   Blo + gb);
        }
    };

    float acc[4][4][4] = {};

    load_chunk(0); CP_COMMIT();
    load_chunk(1); CP_COMMIT();

    for (int c = 0; c < nchunks; ++c) {
        if (c + 2 < nchunks) load_chunk(c + 2);
        CP_COMMIT();
        asm volatile("cp.async.wait_group 2;" ::: "memory");
        __syncthreads();

        const uint32_t stb = sb + (c % NSTAGE) * STAGE_BYTES;
        const uint32_t aH = stb, aL = stb + TILE_B, bH = stb + 2*TILE_B, bL = stb + 3*TILE_B;
        const int lrow = lane & 15, lg = lane >> 4;

        #pragma unroll
        for (int ks = 0; ks < 4; ++ks) {
            const int kkg = ks * 2;
            uint32_t Ah[4][4], Al[4][4], Bh[2][4], Bl[2][4];
            #pragma unroll
            for (int mt = 0; mt < 4; ++mt) {
                int row = warp_m * 64 + mt * 16 + lrow;
                uint32_t so = swz(row, kkg + lg);
                ldsm4(Ah[mt], aH + so);
                ldsm4(Al[mt], aL + so);
            }
            #pragma unroll
            for (int nt2 = 0; nt2 < 2; ++nt2) {
                int row = warp_n * 32 + nt2 * 16 + lrow;
                uint32_t so = swz(row, kkg + lg);
                ldsm4(Bh[nt2], bH + so);
                ldsm4(Bl[nt2], bL + so);
            }
            #pragma unroll
            for (int mt = 0; mt < 4; ++mt) {
                #pragma unroll
                for (int nt = 0; nt < 4; ++nt) {
                    const int j = nt >> 1, h = nt & 1;
                    mma16816(acc[mt][nt], Ah[mt], Bh[j][h], Bh[j][h+2]);
                    mma16816(acc[mt][nt], Ah[mt], Bl[j][h], Bl[j][h+2]);
                    mma16816(acc[mt][nt], Al[mt], Bh[j][h], Bh[j][h+2]);
                }
            }
        }
        __syncthreads();
    }

    #pragma unroll
    for (int mt = 0; mt < 4; ++mt) {
        #pragma unroll
        for (int nt = 0; nt < 4; ++nt) {
            const int m0 = bm + warp_m * 64 + mt * 16 + (lane >> 2);
            const int n0 = bn + warp_n * 32 + nt * 8 + (lane & 3) * 2;
            #pragma unroll
            for (int half = 0; half < 2; ++half) {
                const int m = m0 + half * 8;
                float2 v = make_float2(acc[mt][nt][half*2], acc[mt][nt][half*2+1]);
                if (MODE == 1) {
                    v.x = v.x / (1.f + __expf(-v.x));
                    v.y = v.y / (1.f + __expf(-v.y));
                }
                if (MODE == 2) {
                    float2 a = *reinterpret_cast<const float2*>(aux + (size_t)m * N + n0);
                    v.x += a.x; v.y += a.y;
                }
                *reinterpret_cast<float2*>(C + (size_t)m * N + n0) = v;
            }
        }
    }
}

// ---------------- tensor-core causal silu-attention (bf16x3) ----------------
// grid (16 qtiles, H, B); 8 warps; warp = one m16 row-tile; 2-stage k/v pipe.
#define ATT_SMEM (2*16384 + 2*32768)   // Qh,Ql + 2 stages of {Kh,Kl,Vh,Vl}

__global__ void __launch_bounds__(256, 1)
attn_mma(const float* __restrict__ pbias) {
    extern __shared__ char sm[];
    const uint32_t sb = smem_u32(sm);
    const int tid = threadIdx.x, lane = tid & 31, w = tid >> 5;
    const int qb = (int)gridDim.x - 1 - (int)blockIdx.x;   // big tiles first
    const int h = blockIdx.y, b = blockIdx.z;
    const size_t plane = ((size_t)b*HH + h) * SS * 64;
    const int ktmax = 2*qb + 1;

    const uint32_t QH = sb, QL = sb + 16384;
    const uint32_t ST0 = sb + 32768;

    // Q load (group 0 also contains kv stage 0)
    #pragma unroll
    for (int i = 0; i < 4; i++) {
        int idx = tid + i*256;                 // 1024 granules
        int r = idx >> 3, g = idx & 7;
        size_t goff = plane + (size_t)(qb*128 + r)*64 + g*8;
        cp16(QH + swz(r,g), buf_q_hi + goff);
        cp16(QL + swz(r,g), buf_q_lo + goff);
    }
    auto load_kv = [&](int kt) {
        uint32_t stb = ST0 + (kt & 1) * 32768;
        #pragma unroll
        for (int i = 0; i < 2; i++) {          // 512 granules per tensor
            int idx = tid + i*256;
            int r = idx >> 3, g = idx & 7;
            size_t goff = plane + (size_t)(kt*64 + r)*64 + g*8;
            uint32_t so = swz(r, g);
            cp16(stb + so,         buf_k_hi + goff);
            cp16(stb + 8192 + so,  buf_k_lo + goff);
            cp16(stb + 16384 + so, buf_v_hi + goff);
            cp16(stb + 24576 + so, buf_v_lo + goff);
        }
    };
    load_kv(0); CP_COMMIT();

    float O[8][4] = {};
    const int lrow = lane & 15, lg = lane >> 4;
    const int crow = lane >> 2, ccol = 2*(lane & 3);
    const int qg0 = qb*128 + w*16;

    for (int kt = 0; kt <= ktmax; kt++) {
        if (kt < ktmax) {
            load_kv(kt + 1); CP_COMMIT();
            asm volatile("cp.async.wait_group 1;" ::: "memory");
        } else {
            asm volatile("cp.async.wait_group 0;" ::: "memory");
        }
        __syncthreads();
        const uint32_t stb = ST0 + (kt & 1) * 32768;

        // ---- S = Qh*Kh + Qh*Kl + Ql*Kh  (m16 x 64) ----
        float Sf[8][4] = {};
        #pragma unroll
        for (int ks = 0; ks < 4; ks++) {
            uint32_t qhf[4], qlf[4];
            {
                uint32_t so = swz(w*16 + lrow, 2*ks + lg);
                ldsm4(qhf, QH + so);
                ldsm4(qlf, QL + so);
            }
            #pragma unroll
            for (int n2 = 0; n2 < 4; n2++) {
                uint32_t khf[4], klf[4];
                uint32_t so = swz(n2*16 + lrow, 2*ks + lg);
                ldsm4(khf, stb + so);
                ldsm4(klf, stb + 8192 + so);
                #pragma unroll
                for (int hh = 0; hh < 2; hh++) {
                    mma16816(Sf[2*n2+hh], qhf, khf[hh], khf[hh+2]);
                    mma16816(Sf[2*n2+hh], qhf, klf[hh], klf[hh+2]);
                    mma16816(Sf[2*n2+hh], qlf, khf[hh], khf[hh+2]);
                }
            }
        }

        // ---- bias + causal + silu ----
        const bool diag = (kt >= 2*qb);
        #pragma unroll
        for (int nt = 0; nt < 8; nt++) {
            const int kg = kt*64 + nt*8 + ccol;
            #pragma unroll
            for (int half = 0; half < 2; half++) {
                const int qg = qg0 + crow + half*8;
                float2 bb = *reinterpret_cast<const float2*>(
                    pbias + ((size_t)h*SS + qg)*SS + kg);
                float s0 = Sf[nt][2*half]   + bb.x;
                float s1 = Sf[nt][2*half+1] + bb.y;
                s0 = s0 / (1.f + __expf(-s0));
                s1 = s1 / (1.f + __expf(-s1));
                if (diag) {
                    if (kg     > qg) s0 = 0.f;
                    if (kg + 1 > qg) s1 = 0.f;
                }
                Sf[nt][2*half] = s0; Sf[nt][2*half+1] = s1;
            }
        }

        // ---- split P into hi/lo A-fragments ----
        uint32_t aH[4][4], aL[4][4];
        #pragma unroll
        for (int t = 0; t < 4; t++) {
            #pragma unroll
            for (int rr = 0; rr < 2; rr++) {
                #pragma unroll
                for (int half = 0; half < 2; half++) {
                    float c0 = Sf[2*t+rr][2*half], c1 = Sf[2*t+rr][2*half+1];
                    uint32_t u0 = __float_as_uint(c0), u1 = __float_as_uint(c1);
                    uint32_t hi;
                    asm("prmt.b32 %0, %1, %2, 0x7632;" : "=r"(hi) : "r"(u0), "r"(u1));
                    float l0 = c0 - __uint_as_float(u0 & 0xffff0000u);
                    float l1 = c1 - __uint_as_float(u1 & 0xffff0000u);
                    uint32_t lo;
                    asm("cvt.rn.bf16x2.f32 %0, %1, %2;" : "=r"(lo) : "f"(l1), "f"(l0));
                    aH[t][2*rr + half] = hi;
                    aL[t][2*rr + half] = lo;
                }
            }
        }
        // fix fragment ordering: a0 = tile(2t) rows0-7, a1 = tile(2t) rows8-15,
        // a2 = tile(2t+1) rows0-7, a3 = tile(2t+1) rows8-15.
        // Above loop produced [rr(tile)][half(rows)] at index 2*rr+half — correct.

        // ---- O += Ph*Vh + Ph*Vl + Pl*Vh ----
        #pragma unroll
        for (int t = 0; t < 4; t++) {
            #pragma unroll
            for (int dg = 0; dg < 4; dg++) {
                uint32_t vhf[4], vlf[4];
                uint32_t so = swz(t*16 + lrow, 2*dg + lg);
                ldsm4t(vhf, stb + 16384 + so);
                ldsm4t(vlf, stb + 24576 + so);
                #pragma unroll
                for (int dd = 0; dd < 2; dd++) {
                    mma16816(O[2*dg+dd], aH[t], vhf[2*dd], vhf[2*dd+1]);
                    mma16816(O[2*dg+dd], aH[t], vlf[2*dd], vlf[2*dd+1]);
                    mma16816(O[2*dg+dd], aL[t], vhf[2*dd], vhf[2*dd+1]);
                }
            }
        }
        __syncthreads();
    }

    // ---- write O to buf_attn [b, q, h*64+d] fp32 ----
    #pragma unroll
    for (int dt = 0; dt < 8; dt++) {
        #pragma unroll
        for (int half = 0; half < 2; half++) {
            const int q = qg0 + crow + half*8;
            const int d = dt*8 + ccol;
            float2 v = make_float2(O[dt][2*half], O[dt][2*half+1]);
            *reinterpret_cast<float2*>(buf_attn + ((size_t)b*SS + q)*DD + h*64 + d) = v;
        }
    }
}

// ---------------- elementwise (write hi/lo) ----------------------------------
__global__ void mul_hilo() {
    int i = blockIdx.x * blockDim.x + threadIdx.x;       // per float4
    float4 a = reinterpret_cast<const float4*>(buf_attn)[i];
    float4 u = reinterpret_cast<const float4*>(buf_u)[i];
    __nv_bfloat16 h[4], l[4];
    split1(a.x*u.x, h[0], l[0]); split1(a.y*u.y, h[1], l[1]);
    split1(a.z*u.z, h[2], l[2]); split1(a.w*u.w, h[3], l[3]);
    reinterpret_cast<uint2*>(buf_ams_hi)[i] = *reinterpret_cast<uint2*>(h);
    reinterpret_cast<uint2*>(buf_ams_lo)[i] = *reinterpret_cast<uint2*>(l);
}

__global__ void swiglu_hilo() {
    int i = blockIdx.x * blockDim.x + threadIdx.x;       // per float4 of hidden
    int m = i >> 8, d4 = i & 255;                        // DD/4 = 256
    float4 a  = reinterpret_cast<const float4*>(buf_x12)[(size_t)m*512 + d4];
    float4 b2 = reinterpret_cast<const float4*>(buf_x12)[(size_t)m*512 + 256 + d4];
    float r0 = a.x / (1.f + __expf(-a.x)) * b2.x;
    float r1 = a.y / (1.f + __expf(-a.y)) * b2.y;
    float r2 = a.z / (1.f + __expf(-a.z)) * b2.z;
    float r3 = a.w / (1.f + __expf(-a.w)) * b2.w;
    __nv_bfloat16 h[4], l[4];
    split1(r0, h[0], l[0]); split1(r1, h[1], l[1]);
    split1(r2, h[2], l[2]); split1(r3, h[3], l[3]);
    reinterpret_cast<uint2*>(buf_hid_hi)[i] = *reinterpret_cast<uint2*>(h);
    reinterpret_cast<uint2*>(buf_hid_lo)[i] = *reinterpret_cast<uint2*>(l);
}

// ---------------- launch ------------------------------------------------------
extern "C" void kernel_launch(void* const* d_in, const int* in_sizes, int n_in,
                              void* d_out, int out_size) {
    const float* x      = (const float*)d_in[0];
    const float* p_bias = (const float*)d_in[1];
    // d_in[2] = mask : exactly causal; handled analytically in attn_mma
    const float* w_qkv  = (const float*)d_in[3];
    const float* w_u    = (const float*)d_in[4];
    const float* gams   = (const float*)d_in[5];
    const float* w0     = (const float*)d_in[6];
    const float* w1     = (const float*)d_in[7];
    const float* w3     = (const float*)d_in[8];
    const float* gmffn  = (const float*)d_in[9];
    float* out = (float*)d_out;

    float *qkv, *attn, *u, *o, *x12;
    __nv_bfloat16 *xnh, *xnl, *onh, *onl, *amsh, *amsl, *hidh, *hidl;
    __nv_bfloat16 *wqkvh, *wqkvl, *wuh, *wul, *w0h, *w0l, *w1h, *w1l, *w3h, *w3l;
    cudaGetSymbolAddress((void**)&qkv,  buf_qkv);
    cudaGetSymbolAddress((void**)&attn, buf_attn);
    cudaGetSymbolAddress((void**)&u,    buf_u);
    cudaGetSymbolAddress((void**)&o,    buf_o);
    cudaGetSymbolAddress((void**)&x12,  buf_x12);
    cudaGetSymbolAddress((void**)&xnh,  buf_xn_hi);  cudaGetSymbolAddress((void**)&xnl,  buf_xn_lo);
    cudaGetSymbolAddress((void**)&onh,  buf_on_hi);  cudaGetSymbolAddress((void**)&onl,  buf_on_lo);
    cudaGetSymbolAddress((void**)&amsh, buf_ams_hi); cudaGetSymbolAddress((void**)&amsl, buf_ams_lo);
    cudaGetSymbolAddress((void**)&hidh, buf_hid_hi); cudaGetSymbolAddress((void**)&hidl, buf_hid_lo);
    cudaGetSymbolAddress((void**)&wqkvh, wqkv_hi);   cudaGetSymbolAddress((void**)&wqkvl, wqkv_lo);
    cudaGetSymbolAddress((void**)&wuh,   wu_hi);     cudaGetSymbolAddress((void**)&wul,   wu_lo);
    cudaGetSymbolAddress((void**)&w0h,   w0_hi);     cudaGetSymbolAddress((void**)&w0l,   w0_lo);
    cudaGetSymbolAddress((void**)&w1h,   w1_hi);     cudaGetSymbolAddress((void**)&w1l,   w1_lo);
    cudaGetSymbolAddress((void**)&w3h,   w3_hi);     cudaGetSymbolAddress((void**)&w3l,   w3_lo);

    cudaFuncSetAttribute(gemm_bf16x3<0>, cudaFuncAttributeMaxDynamicSharedMemorySize, GEMM_SMEM);
    cudaFuncSetAttribute(gemm_bf16x3<1>, cudaFuncAttributeMaxDynamicSharedMemorySize, GEMM_SMEM);
    cudaFuncSetAttribute(gemm_bf16x3<2>, cudaFuncAttributeMaxDynamicSharedMemorySize, GEMM_SMEM);
    cudaFuncSetAttribute(attn_mma, cudaFuncAttributeMaxDynamicSharedMemorySize, ATT_SMEM);

    // 0) weight conversions (fp32 -> bf16 hi/lo)
    cvt_hilo<<<(3*DD*DD/4 + 255)/256, 256>>>(w_qkv, wqkvh, wqkvl, 3*DD*DD/4);
    cvt_hilo<<<(DD*DD/4   + 255)/256, 256>>>(w_u,   wuh,   wul,   DD*DD/4);
    cvt_hilo<<<(DD*DD/4   + 255)/256, 256>>>(w0,    w0h,   w0l,   DD*DD/4);
    cvt_hilo<<<(2*DD*DD/4 + 255)/256, 256>>>(w1,    w1h,   w1l,   2*DD*DD/4);
    cvt_hilo<<<(DD*DD/4   + 255)/256, 256>>>(w3,    w3h,   w3l,   DD*DD/4);

    // 1) xn = rmsnorm(x, g_ams) -> hi/lo
    rmsnorm_hilo<<<MM, 256>>>(x, gams, xnh, xnl);
    // 2) qkv = xn @ w_qkv^T (fp32 out)
    gemm_bf16x3<0><<<dim3(3*DD/128, MM/128), 256, GEMM_SMEM>>>(xnh, xnl, wqkvh, wqkvl, nullptr, qkv, MM, 3*DD, DD);
    // 2b) split q/k/v into hi/lo bf16 planes [B,H,S,64]
    cvt_qkv<<<MM*3*DD/4/256, 256>>>();
    // 3) attn = silu-attention (tensor cores)
    attn_mma<<<dim3(SS/128, HH, BB), 256, ATT_SMEM>>>(p_bias);
    // 4) u = silu(xn @ w_u^T)
    gemm_bf16x3<1><<<dim3(DD/128, MM/128), 256, GEMM_SMEM>>>(xnh, xnl, wuh, wul, nullptr, u, MM, DD, DD);
    // 5) ams = attn * u -> hi/lo
    mul_hilo<<<MM*DD/4/256, 256>>>();
    // 6) o = ams @ w0^T + x
    gemm_bf16x3<2><<<dim3(DD/128, MM/128), 256, GEMM_SMEM>>>(amsh, amsl, w0h, w0l, x, o, MM, DD, DD);
    // 7) on = rmsnorm(o, g_mffn) -> hi/lo
    rmsnorm_hilo<<<MM, 256>>>(o, gmffn, onh, onl);
    // 8) x12 = on @ w1^T
    gemm_bf16x3<0><<<dim3(2*DD/128, MM/128), 256, GEMM_SMEM>>>(onh, onl, w1h, w1l, nullptr, x12, MM, 2*DD, DD);
    // 9) hidden = silu(x1) * x2 -> hi/lo
    swiglu_hilo<<<MM*DD/4/256, 256>>>();
    // 10) out = hidden @ w3^T + o
    gemm_bf16x3<2><<<dim3(DD/128, MM/128), 256, GEMM_SMEM>>>(hidh, hidl, w3h, w3l, o, out, MM, DD, DD);
}